// round 1
// baseline (speedup 1.0000x reference)
#include <cuda_runtime.h>
#include <math.h>

#define NPTS 65536
#define KNN  16
#define DCH  96
#define HCH  384
#define HD   256

// ---------------- scratch (allocation-free: device globals) ----------------
__device__ float g_f[(size_t)NPTS * DCH];   // running feature [N,96]
__device__ float g_y[(size_t)NPTS * DCH];   // LFP projection scratch [N,96]
__device__ float g_h[(size_t)NPTS * HCH];   // MLP hidden scratch [N,384]

__device__ __forceinline__ float gelu_exact(float v) {
    return 0.5f * v * (1.0f + erff(v * 0.70710678118654752440f));
}

// ---------------- neighbor embedding: per-edge MLP + 16-way max ----------------
// 128 threads/block = 8 points x 16 edges. Each thread runs the 7->16->32->96
// MLP for one edge; channels computed in 3 chunks of 32 with a 16-lane
// butterfly max reduction.
__global__ void nbr_embed_kernel(
    const float* __restrict__ x, const float* __restrict__ xyz,
    const int* __restrict__ knn,
    const float* __restrict__ w1, const float* __restrict__ g1, const float* __restrict__ b1,
    const float* __restrict__ w2, const float* __restrict__ g2, const float* __restrict__ b2,
    const float* __restrict__ w3,
    const float* __restrict__ ng, const float* __restrict__ nb,
    float* __restrict__ f)
{
    __shared__ float sw1[7 * 16];
    __shared__ float sg1[16], sb1[16];
    __shared__ float sw2[16 * 32];
    __shared__ float sg2[32], sb2[32];
    __shared__ float sw3[32 * 96];
    __shared__ float sng[96], snb[96];

    const int tid = threadIdx.x;
    for (int i = tid; i < 7 * 16; i += 128) sw1[i] = w1[i];
    if (tid < 16) { sg1[tid] = g1[tid]; sb1[tid] = b1[tid]; }
    for (int i = tid; i < 16 * 32; i += 128) sw2[i] = w2[i];
    if (tid < 32) { sg2[tid] = g2[tid]; sb2[tid] = b2[tid]; }
    for (int i = tid; i < 32 * 96; i += 128) sw3[i] = w3[i];
    if (tid < 96) { sng[tid] = ng[tid]; snb[tid] = nb[tid]; }
    __syncthreads();

    const int n = blockIdx.x * 8 + (tid >> 4);
    const int k = tid & 15;
    const int j = knn[n * KNN + k];

    float v[7];
    v[0] = xyz[j * 3 + 0] - xyz[n * 3 + 0];
    v[1] = xyz[j * 3 + 1] - xyz[n * 3 + 1];
    v[2] = xyz[j * 3 + 2] - xyz[n * 3 + 2];
    v[3] = x[j * 4 + 0];
    v[4] = x[j * 4 + 1];
    v[5] = x[j * 4 + 2];
    v[6] = x[j * 4 + 3];

    float h1[16];
#pragma unroll
    for (int o = 0; o < 16; o++) {
        float s = 0.f;
#pragma unroll
        for (int i = 0; i < 7; i++) s += v[i] * sw1[i * 16 + o];
        h1[o] = gelu_exact(s * sg1[o] + sb1[o]);
    }

    float h2[32];
#pragma unroll
    for (int o = 0; o < 32; o++) {
        float s = 0.f;
#pragma unroll
        for (int i = 0; i < 16; i++) s += h1[i] * sw2[i * 32 + o];
        h2[o] = gelu_exact(s * sg2[o] + sb2[o]);
    }

#pragma unroll
    for (int ch = 0; ch < 3; ch++) {
        float acc[32];
#pragma unroll
        for (int o = 0; o < 32; o++) acc[o] = 0.f;
#pragma unroll
        for (int i = 0; i < 32; i++) {
            const float hv = h2[i];
#pragma unroll
            for (int o = 0; o < 32; o++) acc[o] += hv * sw3[i * 96 + ch * 32 + o];
        }
        // 16-lane butterfly max (stays within each 16-lane edge group)
#pragma unroll
        for (int off = 8; off >= 1; off >>= 1) {
#pragma unroll
            for (int o = 0; o < 32; o++)
                acc[o] = fmaxf(acc[o], __shfl_xor_sync(0xffffffffu, acc[o], off));
        }
        if (k == 0) {
#pragma unroll
            for (int o = 0; o < 32; o++) {
                const int c = ch * 32 + o;
                f[(size_t)n * DCH + c] = acc[o] * sng[c] + snb[c];
            }
        }
    }
}

// ---------------- generic tiled GEMM, C[M,Nc] = epi(A[M,K] @ W[K,Nc]) ----------------
// EPI: 0 = plain; 1 = gelu(acc + bias[n]); 2 = C += acc*g[n] + b[n] (residual-BN)
// ABN: apply a = a*gA[k] + bA[k] on A load (folds the head BN into the GEMM)
// Tile: BM=128, BN=32, BK=32, 128 threads, each thread 8x4 outputs.
// Requires M%128==0, K%32==0, Nc%32==0 (true for all shapes here).
template <int EPI, bool ABN>
__global__ void gemm128x32(
    const float* __restrict__ A, const float* __restrict__ W,
    float* __restrict__ C,
    const float* __restrict__ e1, const float* __restrict__ e2,
    const float* __restrict__ gA, const float* __restrict__ bA,
    int M, int K, int Nc)
{
    constexpr int BM = 128, BN = 32, BK = 32;
    __shared__ float As[BM][BK + 1];
    __shared__ float Ws[BK][BN];

    const int tid = threadIdx.x;            // 128
    const int m0 = blockIdx.y * BM;
    const int n0 = blockIdx.x * BN;
    const int ty = tid >> 3;                 // 0..15  (m group)
    const int tx = tid & 7;                  // 0..7   (n group)

    float acc[8][4];
#pragma unroll
    for (int i = 0; i < 8; i++)
#pragma unroll
        for (int jj = 0; jj < 4; jj++) acc[i][jj] = 0.f;

    for (int k0 = 0; k0 < K; k0 += BK) {
        // A tile: 128x32, coalesced over k
#pragma unroll
        for (int i = 0; i < 32; i++) {
            const int e = i * 128 + tid;
            const int m = e >> 5, kk = e & 31;
            float a = A[(size_t)(m0 + m) * K + (k0 + kk)];
            if (ABN) a = a * gA[k0 + kk] + bA[k0 + kk];
            As[m][kk] = a;
        }
        // W tile: 32x32, coalesced over n
#pragma unroll
        for (int i = 0; i < 8; i++) {
            const int e = i * 128 + tid;
            const int kk = e >> 5, nn = e & 31;
            Ws[kk][nn] = W[(size_t)(k0 + kk) * Nc + (n0 + nn)];
        }
        __syncthreads();

#pragma unroll
        for (int kk = 0; kk < BK; kk++) {
            float a[8], w[4];
#pragma unroll
            for (int i = 0; i < 8; i++) a[i] = As[ty * 8 + i][kk];
#pragma unroll
            for (int jj = 0; jj < 4; jj++) w[jj] = Ws[kk][tx * 4 + jj];
#pragma unroll
            for (int i = 0; i < 8; i++)
#pragma unroll
                for (int jj = 0; jj < 4; jj++) acc[i][jj] += a[i] * w[jj];
        }
        __syncthreads();
    }

#pragma unroll
    for (int i = 0; i < 8; i++) {
        const int m = m0 + ty * 8 + i;
#pragma unroll
        for (int jj = 0; jj < 4; jj++) {
            const int nn = n0 + tx * 4 + jj;
            const size_t idx = (size_t)m * Nc + nn;
            float vv = acc[i][jj];
            if (EPI == 1)       vv = gelu_exact(vv + e1[nn]);
            else if (EPI == 2)  vv = C[idx] + vv * e1[nn] + e2[nn];
            C[idx] = vv;
        }
    }
}

// ---------------- LFP edge: f += bn(max_k y[knn[n,k]] - y[n]) ----------------
// one warp per point; lane handles channels c, c+32, c+64
__global__ void lfp_edge_kernel(
    const float* __restrict__ y, const int* __restrict__ knn,
    const float* __restrict__ g, const float* __restrict__ b,
    float* __restrict__ f)
{
    const int warp = (blockIdx.x * blockDim.x + threadIdx.x) >> 5;
    const int lane = threadIdx.x & 31;
    const int n = warp;

    float m0 = -3.402823466e38f, m1 = m0, m2 = m0;
#pragma unroll
    for (int k = 0; k < KNN; k++) {
        const int j = knn[n * KNN + k];
        const float* yr = y + (size_t)j * DCH;
        m0 = fmaxf(m0, yr[lane]);
        m1 = fmaxf(m1, yr[lane + 32]);
        m2 = fmaxf(m2, yr[lane + 64]);
    }
    const float* yn = y + (size_t)n * DCH;
    float* fn = f + (size_t)n * DCH;
    fn[lane]      += (m0 - yn[lane])      * g[lane]      + b[lane];
    fn[lane + 32] += (m1 - yn[lane + 32]) * g[lane + 32] + b[lane + 32];
    fn[lane + 64] += (m2 - yn[lane + 64]) * g[lane + 64] + b[lane + 64];
}

// ---------------- host ----------------
static inline void run_mlp(const float* fbuf, float* hbuf, float* fout,
                           const float* w1, const float* b1,
                           const float* w2, const float* g, const float* b)
{
    // h = gelu(f @ w1 + b1)   [N,384]
    gemm128x32<1, false><<<dim3(HCH / 32, NPTS / 128), 128>>>(
        fbuf, w1, hbuf, b1, nullptr, nullptr, nullptr, NPTS, DCH, HCH);
    // f += bn(h @ w2)
    gemm128x32<2, false><<<dim3(DCH / 32, NPTS / 128), 128>>>(
        hbuf, w2, fout, g, b, nullptr, nullptr, NPTS, HCH, DCH);
}

extern "C" void kernel_launch(void* const* d_in, const int* in_sizes, int n_in,
                              void* d_out, int out_size)
{
    const float* x      = (const float*)d_in[0];
    const float* xyz    = (const float*)d_in[1];
    const int*   knn    = (const int*)  d_in[2];
    const float* ne_w1  = (const float*)d_in[3];
    const float* ne_g1  = (const float*)d_in[4];
    const float* ne_b1  = (const float*)d_in[5];
    const float* ne_w2  = (const float*)d_in[6];
    const float* ne_g2  = (const float*)d_in[7];
    const float* ne_b2  = (const float*)d_in[8];
    const float* ne_w3  = (const float*)d_in[9];
    const float* nbr_g  = (const float*)d_in[10];
    const float* nbr_b  = (const float*)d_in[11];
    const float* m0_w1  = (const float*)d_in[12];
    const float* m0_b1  = (const float*)d_in[13];
    const float* m0_w2  = (const float*)d_in[14];
    const float* m0_g   = (const float*)d_in[15];
    const float* m0_b   = (const float*)d_in[16];
    const float* lfp_w  = (const float*)d_in[17];
    const float* lfp_g  = (const float*)d_in[18];
    const float* lfp_b  = (const float*)d_in[19];
    const float* ms_w1  = (const float*)d_in[20];
    const float* ms_b1  = (const float*)d_in[21];
    const float* ms_w2  = (const float*)d_in[22];
    const float* ms_g   = (const float*)d_in[23];
    const float* ms_b   = (const float*)d_in[24];
    const float* pp_g   = (const float*)d_in[25];
    const float* pp_b   = (const float*)d_in[26];
    const float* pp_w   = (const float*)d_in[27];
    float* out = (float*)d_out;

    float *f, *y, *h;
    cudaGetSymbolAddress((void**)&f, g_f);
    cudaGetSymbolAddress((void**)&y, g_y);
    cudaGetSymbolAddress((void**)&h, g_h);

    // stage 1: neighbor embedding -> f [N,96]
    nbr_embed_kernel<<<NPTS / 8, 128>>>(
        x, xyz, knn,
        ne_w1, ne_g1, ne_b1, ne_w2, ne_g2, ne_b2, ne_w3,
        nbr_g, nbr_b, f);

    // stage 2: f += mlp0(f)
    run_mlp(f, h, f, m0_w1, m0_b1, m0_w2, m0_g, m0_b);

    // stage 3: DEPTH=4 LFP blocks (+ MLP every 2nd)
    for (int i = 0; i < 4; i++) {
        // y = f @ lfp_w[i]
        gemm128x32<0, false><<<dim3(DCH / 32, NPTS / 128), 128>>>(
            f, lfp_w + (size_t)i * DCH * DCH, y,
            nullptr, nullptr, nullptr, nullptr, NPTS, DCH, DCH);
        // f += bn(max_k y[knn] - y)
        lfp_edge_kernel<<<NPTS / 8, 256>>>(
            y, knn, lfp_g + i * DCH, lfp_b + i * DCH, f);
        if (i & 1) {
            const int jj = i / 2;
            run_mlp(f, h, f,
                    ms_w1 + (size_t)jj * DCH * HCH, ms_b1 + (size_t)jj * HCH,
                    ms_w2 + (size_t)jj * HCH * DCH, ms_g + jj * DCH, ms_b + jj * DCH);
        }
    }

    // stage 4: out = bn(f) @ pp_w   (BN folded into A load)
    gemm128x32<0, true><<<dim3(HD / 32, NPTS / 128), 128>>>(
        f, pp_w, out, nullptr, nullptr, pp_g, pp_b, NPTS, DCH, HD);
}